// round 11
// baseline (speedup 1.0000x reference)
#include <cuda_runtime.h>
#include <cstdint>

#define Pn   64
#define Sn   4096
#define Dn   128
#define TM   16          // sample rows per block
#define NTHR 256
#define RPAD 20          // padded k-major activation col stride (multiple of 4, conflict-free)

// -------- persistent folded weights (no allocs allowed) --------
__device__ float gA[Dn * Dn];     // gA[d][col] : scores = x @ gA + gc
__device__ float gB[Dn * Dn];     // gB[col][j] : h = relu(alpha @ gB + bo)
__device__ float gWfcT[Dn * Dn];  // gWfcT[k][c] = Wfc[c][k]
__device__ float gc[Dn];          // folded bq * K^T / 8

// ---------------- f32x2 packed helpers ----------------
__device__ __forceinline__ unsigned long long pack2(float lo, float hi) {
    unsigned long long d;
    asm("mov.b64 %0, {%1, %2};" : "=l"(d)
        : "r"(__float_as_uint(lo)), "r"(__float_as_uint(hi)));
    return d;
}
__device__ __forceinline__ void unpack2(unsigned long long v, float& lo, float& hi) {
    unsigned a, b;
    asm("mov.b64 {%0, %1}, %2;" : "=r"(a), "=r"(b) : "l"(v));
    lo = __uint_as_float(a); hi = __uint_as_float(b);
}
#define FMA2(d, a, b) asm("fma.rn.f32x2 %0, %1, %2, %0;" : "+l"(d) : "l"(a), "l"(b))
#define ADD2(d, a)    asm("add.rn.f32x2 %0, %0, %1;"     : "+l"(d) : "l"(a))
#define CP_COMMIT()   asm volatile("cp.async.commit_group;" ::: "memory")
#define CP_WAIT0()    asm volatile("cp.async.wait_group 0;" ::: "memory")

// ============================================================
// Single precompute kernel: grid = 128 (one col = (h,p) each), 256 threads.
// ============================================================
__global__ __launch_bounds__(NTHR) void pre_all_kernel(
    const float* __restrict__ proxies,
    const float* __restrict__ Wq, const float* __restrict__ bq,
    const float* __restrict__ Wk, const float* __restrict__ bk,
    const float* __restrict__ Wv, const float* __restrict__ bv,
    const float* __restrict__ Wo, const float* __restrict__ Wfc)
{
    __shared__ __align__(16) float prS[Dn];
    __shared__ __align__(16) float kh[64];
    __shared__ __align__(16) float vh[64];

    const int col = blockIdx.x;
    const int h = col >> 6, p = col & 63;
    const int t = threadIdx.x;
    const int w = t >> 5, l = t & 31;

    if (t < 32)
        *reinterpret_cast<float4*>(prS + t * 4) =
            reinterpret_cast<const float4*>(proxies + p * Dn)[t];
    __syncthreads();

    // warp-cooperative dots: warps 0-3 -> kh, warps 4-7 -> vh (16 j's each)
    {
        const float* Wsrc = (w < 4) ? Wk : Wv;
        const float* bsrc = (w < 4) ? bk : bv;
        float* dst = (w < 4) ? kh : vh;
        const int j0 = (w & 3) * 16;
        float4 pv = *reinterpret_cast<const float4*>(prS + l * 4);
#pragma unroll
        for (int jj = 0; jj < 16; jj++) {
            int j = j0 + jj;
            float4 w4 = *reinterpret_cast<const float4*>(Wsrc + (h * 64 + j) * Dn + l * 4);
            float s = w4.x * pv.x + w4.y * pv.y + w4.z * pv.z + w4.w * pv.w;
#pragma unroll
            for (int o = 16; o; o >>= 1) s += __shfl_xor_sync(0xffffffffu, s, o);
            if (l == 0) dst[j] = s + bsrc[h * 64 + j];
        }
    }
    __syncthreads();

    if (w == 0) {   // gc[col]
        float s = bq[h * 64 + l] * kh[l] + bq[h * 64 + 32 + l] * kh[32 + l];
#pragma unroll
        for (int o = 16; o; o >>= 1) s += __shfl_xor_sync(0xffffffffu, s, o);
        if (l == 0) gc[col] = s * 0.125f;
    }

    if (t < Dn) {   // gA column + WfcT column
        float a = 0.f;
#pragma unroll 16
        for (int j = 0; j < 64; j++) a += Wq[(h * 64 + j) * Dn + t] * kh[j];  // coalesced over t
        gA[t * Dn + col] = a * 0.125f;
        gWfcT[t * Dn + col] = Wfc[col * Dn + t];
    } else {        // gB row
        const int j2 = t - Dn;
        const float4* wo = reinterpret_cast<const float4*>(Wo + j2 * Dn + h * 64);
        float s = 0.f;
#pragma unroll
        for (int q = 0; q < 16; q++) {
            float4 w4 = wo[q];
            float4 v4 = *reinterpret_cast<const float4*>(vh + q * 4);
            s += w4.x * v4.x + w4.y * v4.y + w4.z * v4.z + w4.w * v4.w;
        }
        gB[col * Dn + j2] = s;
    }
}

// ============================================================
// Main kernel helpers
// ============================================================
__device__ __forceinline__ void lw_async(float* Wbuf, const float* __restrict__ gW, int tid) {
    unsigned saddr = (unsigned)__cvta_generic_to_shared(Wbuf);
#pragma unroll
    for (int i = 0; i < 16; i++) {
        int idx = tid + i * NTHR;   // float4 index, 4096 total
        asm volatile("cp.async.cg.shared.global [%0], [%1], 16;"
                     :: "r"(saddr + idx * 16), "l"(gW + idx * 4));
    }
}

// k-major GEMM, software-pipelined (prefetch distance 1).
// lane owns rows rbase..rbase+3 (2 f32x2 row-pairs) x cols {c0, c0+1} -> 4 accs.
__device__ __forceinline__ void gemm_t(const float* __restrict__ actT,
                                       const float* __restrict__ Ws,
                                       int rbase, int c0, unsigned long long acc[4])
{
    acc[0] = acc[1] = acc[2] = acc[3] = 0ull;
    const float* xp = actT + rbase;
    const float* wp = Ws + c0;

    ulonglong2 xa = *reinterpret_cast<const ulonglong2*>(xp);
    float2     wv = *reinterpret_cast<const float2*>(wp);
#pragma unroll 8
    for (int k = 0; k < Dn - 1; k++) {
        ulonglong2 xan = *reinterpret_cast<const ulonglong2*>(xp + (k + 1) * RPAD);
        float2     wvn = *reinterpret_cast<const float2*>(wp + (k + 1) * Dn);
        unsigned long long w0d = pack2(wv.x, wv.x);
        unsigned long long w1d = pack2(wv.y, wv.y);
        FMA2(acc[0], xa.x, w0d); FMA2(acc[1], xa.y, w0d);
        FMA2(acc[2], xa.x, w1d); FMA2(acc[3], xa.y, w1d);
        xa = xan; wv = wvn;
    }
    {
        unsigned long long w0d = pack2(wv.x, wv.x);
        unsigned long long w1d = pack2(wv.y, wv.y);
        FMA2(acc[0], xa.x, w0d); FMA2(acc[1], xa.y, w0d);
        FMA2(acc[2], xa.x, w1d); FMA2(acc[3], xa.y, w1d);
    }
}

// ============================================================
// Main fused kernel: 3 chained 16x128x128 GEMM stages + softmax.
// grid=256 (TM=16 rows each), 256 threads, single 64KB weight buffer
// -> 84KB smem/block -> 2 blocks/SM, all 256 blocks co-resident.
// ============================================================
__global__ __launch_bounds__(NTHR, 2) void gnn_main_kernel(
    const float* __restrict__ x,
    const float* __restrict__ bo, const float* __restrict__ bfc,
    float* __restrict__ outP, float* __restrict__ outH)
{
    extern __shared__ float smem[];
    float* actT0 = smem;                    // [128][RPAD]  x tile (k-major), later hT
    float* actT1 = smem + Dn * RPAD;        // [128][RPAD]  scoresT -> alphaT
    float* Wbuf  = smem + 2 * Dn * RPAD;    // 128*128 single buffer: A -> B -> WfcT

    const int tid  = threadIdx.x;
    const int row0 = blockIdx.x * TM;
    const int w = tid >> 5, l = tid & 31;
    const int c0    = w * 16 + (l & 7) * 2;   // 2 cols per lane
    const int rbase = (l >> 3) * 4;           // 4 rows per lane

    // -------- prologue: cp.async A ; stage x transposed into actT0 --------
    lw_async(Wbuf, gA, tid);
    CP_COMMIT();
    {
        const float4* xg = reinterpret_cast<const float4*>(x + (size_t)row0 * Dn);
#pragma unroll
        for (int i = 0; i < 2; i++) {
            int idx = tid + i * NTHR;       // 0..511 float4 of 16x128 tile
            int r = idx >> 5, c4 = idx & 31;
            float4 v = xg[idx];
            actT0[(c4 * 4 + 0) * RPAD + r] = v.x;
            actT0[(c4 * 4 + 1) * RPAD + r] = v.y;
            actT0[(c4 * 4 + 2) * RPAD + r] = v.z;
            actT0[(c4 * 4 + 3) * RPAD + r] = v.w;
        }
    }
    CP_WAIT0();
    __syncthreads();

    unsigned long long acc[4];

    // -------- stage 1: scoresT = (x @ A + c)^T --------
    gemm_t(actT0, Wbuf, rbase, c0, acc);
    {
        float2 cv = *reinterpret_cast<const float2*>(gc + c0);
        unsigned long long cd0 = pack2(cv.x, cv.x);
        unsigned long long cd1 = pack2(cv.y, cv.y);
        ADD2(acc[0], cd0); ADD2(acc[1], cd0);
        ADD2(acc[2], cd1); ADD2(acc[3], cd1);
        ulonglong2 s0; s0.x = acc[0]; s0.y = acc[1];
        ulonglong2 s1; s1.x = acc[2]; s1.y = acc[3];
        *reinterpret_cast<ulonglong2*>(actT1 + c0 * RPAD + rbase)       = s0;
        *reinterpret_cast<ulonglong2*>(actT1 + (c0 + 1) * RPAD + rbase) = s1;
    }
    __syncthreads();                         // all stage-1 reads of Wbuf(A) done

    // -------- refill Wbuf with B ; softmax overlaps the fill --------
    lw_async(Wbuf, gB, tid);
    CP_COMMIT();
    if (tid < 32) {                          // one (row, head) per thread
        const int r = tid >> 1, hh = tid & 1;
        float* sp = actT1 + (hh * 64) * RPAD + r;
        float mx = -1e30f;
#pragma unroll 8
        for (int p = 0; p < 64; p++) mx = fmaxf(mx, sp[p * RPAD]);
        float sum = 0.f;
#pragma unroll 8
        for (int p = 0; p < 64; p++) { float e = __expf(sp[p * RPAD] - mx); sp[p * RPAD] = e; sum += e; }
        float inv = 1.f / sum;
#pragma unroll 8
        for (int p = 0; p < 64; p++) sp[p * RPAD] *= inv;
    }
    CP_WAIT0();
    __syncthreads();

    // -------- stage 2: h = relu(alpha @ B + bo) ; write outH + hT -> actT0 --------
    gemm_t(actT1, Wbuf, rbase, c0, acc);
    {
        float2 bv = *reinterpret_cast<const float2*>(bo + c0);
        float h0[4], h1[4];
#pragma unroll
        for (int rp = 0; rp < 2; rp++) {
            float a, b;
            unpack2(acc[rp], a, b);
            h0[2 * rp]     = fmaxf(a + bv.x, 0.f);
            h0[2 * rp + 1] = fmaxf(b + bv.x, 0.f);
            unpack2(acc[2 + rp], a, b);
            h1[2 * rp]     = fmaxf(a + bv.y, 0.f);
            h1[2 * rp + 1] = fmaxf(b + bv.y, 0.f);
        }
        *reinterpret_cast<float4*>(actT0 + c0 * RPAD + rbase)
            = make_float4(h0[0], h0[1], h0[2], h0[3]);
        *reinterpret_cast<float4*>(actT0 + (c0 + 1) * RPAD + rbase)
            = make_float4(h1[0], h1[1], h1[2], h1[3]);
#pragma unroll
        for (int rr = 0; rr < 4; rr++)
            *reinterpret_cast<float2*>(outH + (size_t)(row0 + rbase + rr) * Dn + c0)
                = make_float2(h0[rr], h1[rr]);
    }
    __syncthreads();                         // all stage-2 reads of Wbuf(B) done

    // -------- refill Wbuf with WfcT --------
    lw_async(Wbuf, gWfcT, tid);
    CP_COMMIT();
    CP_WAIT0();
    __syncthreads();

    // -------- stage 3: preds = h @ Wfc^T + bfc --------
    gemm_t(actT0, Wbuf, rbase, c0, acc);
    {
        float2 bv = *reinterpret_cast<const float2*>(bfc + c0);
#pragma unroll
        for (int rp = 0; rp < 2; rp++) {
            float a, b, a1, b1;
            unpack2(acc[rp], a, b);
            unpack2(acc[2 + rp], a1, b1);
            *reinterpret_cast<float2*>(outP + (size_t)(row0 + rbase + 2 * rp) * Dn + c0)
                = make_float2(a + bv.x, a1 + bv.y);
            *reinterpret_cast<float2*>(outP + (size_t)(row0 + rbase + 2 * rp + 1) * Dn + c0)
                = make_float2(b + bv.x, b1 + bv.y);
        }
    }
}

// ============================================================
// launcher (graph-capturable: kernel launches only)
// ============================================================
extern "C" void kernel_launch(void* const* d_in, const int* in_sizes, int n_in,
                              void* d_out, int out_size) {
    const float* x       = (const float*)d_in[0];
    const float* proxies = (const float*)d_in[1];
    const float* Wq  = (const float*)d_in[2];
    const float* bq  = (const float*)d_in[3];
    const float* Wk  = (const float*)d_in[4];
    const float* bk  = (const float*)d_in[5];
    const float* Wv  = (const float*)d_in[6];
    const float* bv  = (const float*)d_in[7];
    const float* Wo  = (const float*)d_in[8];
    const float* bo  = (const float*)d_in[9];
    const float* Wfc = (const float*)d_in[10];
    const float* bfc = (const float*)d_in[11];
    // d_in[12] = edge_index : dense bipartite structure is known -> unused

    float* outP = (float*)d_out;                 // preds[P:]  (S x D)
    float* outH = outP + (size_t)out_size / 2;   // h[P:]      (S x D)

    pre_all_kernel<<<Dn, NTHR>>>(proxies, Wq, bq, Wk, bk, Wv, bv, Wo, Wfc);

    const int smem_bytes = (2 * Dn * RPAD + Dn * Dn) * (int)sizeof(float);  // ~84 KB
    cudaFuncSetAttribute(gnn_main_kernel,
                         cudaFuncAttributeMaxDynamicSharedMemorySize, smem_bytes);
    gnn_main_kernel<<<Sn / TM, NTHR, smem_bytes>>>(x, bo, bfc, outP, outH);
}

// round 12
// speedup vs baseline: 1.1622x; 1.1622x over previous
#include <cuda_runtime.h>
#include <cstdint>

#define Pn   64
#define Sn   4096
#define Dn   128
#define TM   32          // sample rows per block
#define NTHR 256
#define RPAD 36          // padded k-major activation col stride
#define SLACK 1024       // smem slack floats: benign over-prefetch target

// -------- persistent folded weights (no allocs allowed) --------
__device__ float gA[Dn * Dn];     // gA[d][col] : scores = x @ gA + gc
__device__ float gB[Dn * Dn];     // gB[col][j] : h = relu(alpha @ gB + bo)
__device__ float gWfcT[Dn * Dn];  // gWfcT[k][c] = Wfc[c][k]
__device__ float gc[Dn];          // folded bq * K^T / 8

// ---------------- f32x2 packed helpers ----------------
__device__ __forceinline__ unsigned long long pack2(float lo, float hi) {
    unsigned long long d;
    asm("mov.b64 %0, {%1, %2};" : "=l"(d)
        : "r"(__float_as_uint(lo)), "r"(__float_as_uint(hi)));
    return d;
}
__device__ __forceinline__ void unpack2(unsigned long long v, float& lo, float& hi) {
    unsigned a, b;
    asm("mov.b64 {%0, %1}, %2;" : "=r"(a), "=r"(b) : "l"(v));
    lo = __uint_as_float(a); hi = __uint_as_float(b);
}
#define FMA2(d, a, b) asm("fma.rn.f32x2 %0, %1, %2, %0;" : "+l"(d) : "l"(a), "l"(b))
#define ADD2(d, a)    asm("add.rn.f32x2 %0, %0, %1;"     : "+l"(d) : "l"(a))
#define CP_COMMIT()   asm volatile("cp.async.commit_group;" ::: "memory")
#define CP_WAIT0()    asm volatile("cp.async.wait_group 0;" ::: "memory")

// ============================================================
// Single precompute kernel: grid = 128 (one col = (h,p) each), 256 threads.
// ============================================================
__global__ __launch_bounds__(NTHR) void pre_all_kernel(
    const float* __restrict__ proxies,
    const float* __restrict__ Wq, const float* __restrict__ bq,
    const float* __restrict__ Wk, const float* __restrict__ bk,
    const float* __restrict__ Wv, const float* __restrict__ bv,
    const float* __restrict__ Wo, const float* __restrict__ Wfc)
{
    __shared__ __align__(16) float prS[Dn];
    __shared__ __align__(16) float kh[64];
    __shared__ __align__(16) float vh[64];

    const int col = blockIdx.x;
    const int h = col >> 6, p = col & 63;
    const int t = threadIdx.x;
    const int w = t >> 5, l = t & 31;

    if (t < 32)
        *reinterpret_cast<float4*>(prS + t * 4) =
            reinterpret_cast<const float4*>(proxies + p * Dn)[t];
    __syncthreads();

    // warp-cooperative dots: warps 0-3 -> kh, warps 4-7 -> vh (16 j's each)
    {
        const float* Wsrc = (w < 4) ? Wk : Wv;
        const float* bsrc = (w < 4) ? bk : bv;
        float* dst = (w < 4) ? kh : vh;
        const int j0 = (w & 3) * 16;
        float4 pv = *reinterpret_cast<const float4*>(prS + l * 4);
#pragma unroll
        for (int jj = 0; jj < 16; jj++) {
            int j = j0 + jj;
            float4 w4 = *reinterpret_cast<const float4*>(Wsrc + (h * 64 + j) * Dn + l * 4);
            float s = w4.x * pv.x + w4.y * pv.y + w4.z * pv.z + w4.w * pv.w;
#pragma unroll
            for (int o = 16; o; o >>= 1) s += __shfl_xor_sync(0xffffffffu, s, o);
            if (l == 0) dst[j] = s + bsrc[h * 64 + j];
        }
    }
    __syncthreads();

    if (w == 0) {   // gc[col]
        float s = bq[h * 64 + l] * kh[l] + bq[h * 64 + 32 + l] * kh[32 + l];
#pragma unroll
        for (int o = 16; o; o >>= 1) s += __shfl_xor_sync(0xffffffffu, s, o);
        if (l == 0) gc[col] = s * 0.125f;
    }

    if (t < Dn) {   // gA column + WfcT column
        float a = 0.f;
#pragma unroll 16
        for (int j = 0; j < 64; j++) a += Wq[(h * 64 + j) * Dn + t] * kh[j];  // coalesced over t
        gA[t * Dn + col] = a * 0.125f;
        gWfcT[t * Dn + col] = Wfc[col * Dn + t];
    } else {        // gB row
        const int j2 = t - Dn;
        const float4* wo = reinterpret_cast<const float4*>(Wo + j2 * Dn + h * 64);
        float s = 0.f;
#pragma unroll
        for (int q = 0; q < 16; q++) {
            float4 w4 = wo[q];
            float4 v4 = *reinterpret_cast<const float4*>(vh + q * 4);
            s += w4.x * v4.x + w4.y * v4.y + w4.z * v4.z + w4.w * v4.w;
        }
        gB[col * Dn + j2] = s;
    }
}

// ============================================================
// Main kernel helpers
// ============================================================
__device__ __forceinline__ void lw_async(float* Wbuf, const float* __restrict__ gW, int tid) {
    unsigned saddr = (unsigned)__cvta_generic_to_shared(Wbuf);
#pragma unroll
    for (int i = 0; i < 16; i++) {
        int idx = tid + i * NTHR;   // float4 index, 4096 total
        asm volatile("cp.async.cg.shared.global [%0], [%1], 16;"
                     :: "r"(saddr + idx * 16), "l"(gW + idx * 4));
    }
}

// k-major GEMM with explicit two-buffer register pipeline (distance 2).
// Lane owns rows rbase..rbase+7 (4 f32x2 row-pairs) x cols {c0, c0+1} -> 8 accs.
// Over-prefetches 2 k past the end (reads land in smem slack -> benign).
__device__ __forceinline__ void gemm_t(const float* __restrict__ actT,
                                       const float* __restrict__ Ws,
                                       int rbase, int c0, unsigned long long acc[8])
{
#pragma unroll
    for (int i = 0; i < 8; i++) acc[i] = 0ull;
    const float* xp = actT + rbase;
    const float* wp = Ws + c0;

    ulonglong2 xa0 = *reinterpret_cast<const ulonglong2*>(xp);
    ulonglong2 xb0 = *reinterpret_cast<const ulonglong2*>(xp + 4);
    float2     w0  = *reinterpret_cast<const float2*>(wp);
    ulonglong2 xa1 = *reinterpret_cast<const ulonglong2*>(xp + RPAD);
    ulonglong2 xb1 = *reinterpret_cast<const ulonglong2*>(xp + RPAD + 4);
    float2     w1  = *reinterpret_cast<const float2*>(wp + Dn);

#pragma unroll 2
    for (int k = 0; k < Dn; k += 2) {
        // ---- compute k (buf0), prefetch k+2 -> buf0 ----
        unsigned long long wlo = pack2(w0.x, w0.x);
        unsigned long long whi = pack2(w0.y, w0.y);
        ulonglong2 nxa = *reinterpret_cast<const ulonglong2*>(xp + (k + 2) * RPAD);
        ulonglong2 nxb = *reinterpret_cast<const ulonglong2*>(xp + (k + 2) * RPAD + 4);
        float2     nw  = *reinterpret_cast<const float2*>(wp + (k + 2) * Dn);
        FMA2(acc[0], xa0.x, wlo); FMA2(acc[1], xa0.y, wlo);
        FMA2(acc[2], xb0.x, wlo); FMA2(acc[3], xb0.y, wlo);
        FMA2(acc[4], xa0.x, whi); FMA2(acc[5], xa0.y, whi);
        FMA2(acc[6], xb0.x, whi); FMA2(acc[7], xb0.y, whi);
        xa0 = nxa; xb0 = nxb; w0 = nw;
        // ---- compute k+1 (buf1), prefetch k+3 -> buf1 ----
        wlo = pack2(w1.x, w1.x);
        whi = pack2(w1.y, w1.y);
        nxa = *reinterpret_cast<const ulonglong2*>(xp + (k + 3) * RPAD);
        nxb = *reinterpret_cast<const ulonglong2*>(xp + (k + 3) * RPAD + 4);
        nw  = *reinterpret_cast<const float2*>(wp + (k + 3) * Dn);
        FMA2(acc[0], xa1.x, wlo); FMA2(acc[1], xa1.y, wlo);
        FMA2(acc[2], xb1.x, wlo); FMA2(acc[3], xb1.y, wlo);
        FMA2(acc[4], xa1.x, whi); FMA2(acc[5], xa1.y, whi);
        FMA2(acc[6], xb1.x, whi); FMA2(acc[7], xb1.y, whi);
        xa1 = nxa; xb1 = nxb; w1 = nw;
    }
}

// ============================================================
// Main fused kernel: 3 chained 32x128x128 GEMM stages + softmax.
// grid=128 (TM=32 rows), 256 threads, double-buffered weights via cp.async.
// ============================================================
__global__ __launch_bounds__(NTHR, 1) void gnn_main_kernel(
    const float* __restrict__ x,
    const float* __restrict__ bo, const float* __restrict__ bfc,
    float* __restrict__ outP, float* __restrict__ outH)
{
    extern __shared__ float smem[];
    float* actT0 = smem;                    // [128][RPAD]  x tile (k-major), later hT
    float* actT1 = smem + Dn * RPAD;        // [128][RPAD]  scoresT -> alphaT
    float* W0    = smem + 2 * Dn * RPAD;    // 128*128 : A, then WfcT
    float* W1    = W0 + Dn * Dn;            // 128*128 : B        (+ SLACK after)

    const int tid  = threadIdx.x;
    const int row0 = blockIdx.x * TM;
    const int w = tid >> 5, l = tid & 31;
    const int c0    = w * 16 + (l & 7) * 2;   // 2 cols per lane
    const int rbase = (l >> 3) * 8;           // 8 rows per lane

    // -------- prologue: cp.async A -> W0 ; stage x transposed into actT0 --------
    lw_async(W0, gA, tid);
    CP_COMMIT();
    {
        const float4* xg = reinterpret_cast<const float4*>(x + (size_t)row0 * Dn);
#pragma unroll
        for (int i = 0; i < 4; i++) {
            int idx = tid + i * NTHR;       // 0..1023 float4 of 32x128 tile
            int r = idx >> 5, c4 = idx & 31;
            float4 v = xg[idx];
            actT0[(c4 * 4 + 0) * RPAD + r] = v.x;
            actT0[(c4 * 4 + 1) * RPAD + r] = v.y;
            actT0[(c4 * 4 + 2) * RPAD + r] = v.z;
            actT0[(c4 * 4 + 3) * RPAD + r] = v.w;
        }
    }
    CP_WAIT0();
    __syncthreads();

    unsigned long long acc[8];

    // -------- stage 1: scoresT = (x @ A + c)^T ; prefetch B -> W1 --------
    lw_async(W1, gB, tid);
    CP_COMMIT();
    gemm_t(actT0, W0, rbase, c0, acc);
    {
        float2 cv = *reinterpret_cast<const float2*>(gc + c0);
        unsigned long long cd0 = pack2(cv.x, cv.x);
        unsigned long long cd1 = pack2(cv.y, cv.y);
        ADD2(acc[0], cd0); ADD2(acc[1], cd0); ADD2(acc[2], cd0); ADD2(acc[3], cd0);
        ADD2(acc[4], cd1); ADD2(acc[5], cd1); ADD2(acc[6], cd1); ADD2(acc[7], cd1);
        ulonglong2 s0; s0.x = acc[0]; s0.y = acc[1];
        ulonglong2 s1; s1.x = acc[2]; s1.y = acc[3];
        ulonglong2 s2; s2.x = acc[4]; s2.y = acc[5];
        ulonglong2 s3; s3.x = acc[6]; s3.y = acc[7];
        *reinterpret_cast<ulonglong2*>(actT1 + c0 * RPAD + rbase)           = s0;
        *reinterpret_cast<ulonglong2*>(actT1 + c0 * RPAD + rbase + 4)       = s1;
        *reinterpret_cast<ulonglong2*>(actT1 + (c0 + 1) * RPAD + rbase)     = s2;
        *reinterpret_cast<ulonglong2*>(actT1 + (c0 + 1) * RPAD + rbase + 4) = s3;
    }
    CP_WAIT0();                              // B landed
    __syncthreads();                         // all stage-1 reads of W0(A) done

    // -------- prefetch WfcT -> W0 (overlaps softmax + stage 2) ; softmax --------
    lw_async(W0, gWfcT, tid);
    CP_COMMIT();
    if (tid < 64) {                          // one (row, head) per thread
        const int r = tid >> 1, hh = tid & 1;
        float* sp = actT1 + (hh * 64) * RPAD + r;
        float mx = -1e30f;
#pragma unroll 8
        for (int p = 0; p < 64; p++) mx = fmaxf(mx, sp[p * RPAD]);
        float sum = 0.f;
#pragma unroll 8
        for (int p = 0; p < 64; p++) { float e = __expf(sp[p * RPAD] - mx); sp[p * RPAD] = e; sum += e; }
        float inv = 1.f / sum;
#pragma unroll 8
        for (int p = 0; p < 64; p++) sp[p * RPAD] *= inv;
    }
    __syncthreads();

    // -------- stage 2: h = relu(alpha @ B + bo) ; write outH + hT -> actT0 --------
    gemm_t(actT1, W1, rbase, c0, acc);
    {
        float2 bv = *reinterpret_cast<const float2*>(bo + c0);
        float h0[8], h1[8];
#pragma unroll
        for (int rp = 0; rp < 4; rp++) {
            float a, b;
            unpack2(acc[rp], a, b);
            h0[2 * rp]     = fmaxf(a + bv.x, 0.f);
            h0[2 * rp + 1] = fmaxf(b + bv.x, 0.f);
            unpack2(acc[4 + rp], a, b);
            h1[2 * rp]     = fmaxf(a + bv.y, 0.f);
            h1[2 * rp + 1] = fmaxf(b + bv.y, 0.f);
        }
        *reinterpret_cast<float4*>(actT0 + c0 * RPAD + rbase)
            = make_float4(h0[0], h0[1], h0[2], h0[3]);
        *reinterpret_cast<float4*>(actT0 + c0 * RPAD + rbase + 4)
            = make_float4(h0[4], h0[5], h0[6], h0[7]);
        *reinterpret_cast<float4*>(actT0 + (c0 + 1) * RPAD + rbase)
            = make_float4(h1[0], h1[1], h1[2], h1[3]);
        *reinterpret_cast<float4*>(actT0 + (c0 + 1) * RPAD + rbase + 4)
            = make_float4(h1[4], h1[5], h1[6], h1[7]);
#pragma unroll
        for (int rr = 0; rr < 8; rr++)
            *reinterpret_cast<float2*>(outH + (size_t)(row0 + rbase + rr) * Dn + c0)
                = make_float2(h0[rr], h1[rr]);
    }
    CP_WAIT0();                              // WfcT landed (overlapped with stage 2)
    __syncthreads();                         // all stage-2 reads of W1(B) done

    // -------- stage 3: preds = h @ Wfc^T + bfc --------
    gemm_t(actT0, W0, rbase, c0, acc);
    {
        float2 bv = *reinterpret_cast<const float2*>(bfc + c0);
#pragma unroll
        for (int rp = 0; rp < 4; rp++) {
            float a, b, a1, b1;
            unpack2(acc[rp], a, b);
            unpack2(acc[4 + rp], a1, b1);
            *reinterpret_cast<float2*>(outP + (size_t)(row0 + rbase + 2 * rp) * Dn + c0)
                = make_float2(a + bv.x, a1 + bv.y);
            *reinterpret_cast<float2*>(outP + (size_t)(row0 + rbase + 2 * rp + 1) * Dn + c0)
                = make_float2(b + bv.x, b1 + bv.y);
        }
    }
}

// ============================================================
// launcher (graph-capturable: kernel launches only)
// ============================================================
extern "C" void kernel_launch(void* const* d_in, const int* in_sizes, int n_in,
                              void* d_out, int out_size) {
    const float* x       = (const float*)d_in[0];
    const float* proxies = (const float*)d_in[1];
    const float* Wq  = (const float*)d_in[2];
    const float* bq  = (const float*)d_in[3];
    const float* Wk  = (const float*)d_in[4];
    const float* bk  = (const float*)d_in[5];
    const float* Wv  = (const float*)d_in[6];
    const float* bv  = (const float*)d_in[7];
    const float* Wo  = (const float*)d_in[8];
    const float* bo  = (const float*)d_in[9];
    const float* Wfc = (const float*)d_in[10];
    const float* bfc = (const float*)d_in[11];
    // d_in[12] = edge_index : dense bipartite structure is known -> unused

    float* outP = (float*)d_out;                 // preds[P:]  (S x D)
    float* outH = outP + (size_t)out_size / 2;   // h[P:]      (S x D)

    pre_all_kernel<<<Dn, NTHR>>>(proxies, Wq, bq, Wk, bk, Wv, bv, Wo, Wfc);

    // act tiles + 2 weight buffers + slack for benign over-prefetch
    const int smem_bytes = (2 * Dn * RPAD + 2 * Dn * Dn + SLACK) * (int)sizeof(float); // ~168 KB
    cudaFuncSetAttribute(gnn_main_kernel,
                         cudaFuncAttributeMaxDynamicSharedMemorySize, smem_bytes);
    gnn_main_kernel<<<Sn / TM, NTHR, smem_bytes>>>(x, bo, bfc, outP, outH);
}

// round 15
// speedup vs baseline: 1.5192x; 1.3072x over previous
#include <cuda_runtime.h>
#include <cuda_bf16.h>
#include <cstdint>

#define Pn 64
#define Sn 4096
#define Dn 128
#define TM 32            // sample rows per block
#define NTHR 256
#define XSTR 136         // bf16 operand-tile k-stride (128 + 8 pad) -> conflict-free frags
#define SSTR 132         // fp32 score-tile stride

// ---------------- persistent device scratch (no allocs allowed) ----------------
// bf16 hi/lo operand images, [n][k] k-major with XSTR padding
__device__ __align__(16) uint16_t imgA_hi[Dn * XSTR], imgA_lo[Dn * XSTR];  // stage1 B-op
__device__ __align__(16) uint16_t imgB_hi[Dn * XSTR], imgB_lo[Dn * XSTR];  // stage2 B-op
__device__ __align__(16) uint16_t imgW_hi[Dn * XSTR], imgW_lo[Dn * XSTR];  // stage3 B-op
__device__ __align__(16) float gc[Dn];   // folded bq * K^T / 8 (stage-1 bias)

// ---------------- helpers ----------------
#define CP_COMMIT()  asm volatile("cp.async.commit_group;" ::: "memory")
#define CP_WAIT(n)   asm volatile("cp.async.wait_group %0;" :: "n"(n) : "memory")

__device__ __forceinline__ void cvt_split2(float a0, float a1, uint32_t& hi, uint32_t& lo) {
    asm("cvt.rn.bf16x2.f32 %0, %1, %2;" : "=r"(hi) : "f"(a1), "f"(a0));
    float f0 = __uint_as_float(hi << 16);
    float f1 = __uint_as_float(hi & 0xFFFF0000u);
    asm("cvt.rn.bf16x2.f32 %0, %1, %2;" : "=r"(lo) : "f"(a1 - f1), "f"(a0 - f0));
}
__device__ __forceinline__ void cvt_split4(float a0, float a1, float a2, float a3,
                                           unsigned long long& hi, unsigned long long& lo) {
    uint32_t u0, u1, v0, v1;
    cvt_split2(a0, a1, u0, v0);
    cvt_split2(a2, a3, u1, v1);
    asm("mov.b64 %0, {%1, %2};" : "=l"(hi) : "r"(u0), "r"(u1));
    asm("mov.b64 %0, {%1, %2};" : "=l"(lo) : "r"(v0), "r"(v1));
}

// ============================================================
// Single precompute kernel: grid = 128 (col = h*64+p), 256 threads.
// Folds projections and writes split-bf16 operand images directly:
//   imgA[n=col][k=d] = (1/8) sum_j Wq[h64+j][d] * K[p][h64+j]
//   imgB[n=j][k=col] =       sum_j' V[p][h64+j'] * Wo[j][h64+j']
//   imgW[n=col][k=d] = Wfc[col][d]
//   gc[col]          = (1/8) sum_j bq[h64+j] * K[p][h64+j]
// ============================================================
__global__ __launch_bounds__(NTHR) void pre_all_kernel(
    const float* __restrict__ proxies,
    const float* __restrict__ Wq, const float* __restrict__ bq,
    const float* __restrict__ Wk, const float* __restrict__ bk,
    const float* __restrict__ Wv, const float* __restrict__ bv,
    const float* __restrict__ Wo, const float* __restrict__ Wfc)
{
    __shared__ __align__(16) float prS[Dn];
    __shared__ __align__(16) float kh[64];
    __shared__ __align__(16) float vh[64];

    const int col = blockIdx.x;
    const int h = col >> 6, p = col & 63;
    const int t = threadIdx.x;
    const int w = t >> 5, l = t & 31;

    if (t < 32)
        *reinterpret_cast<float4*>(prS + t * 4) =
            reinterpret_cast<const float4*>(proxies + p * Dn)[t];
    __syncthreads();

    {   // warp-cooperative dots: warps 0-3 -> kh, warps 4-7 -> vh
        const float* Wsrc = (w < 4) ? Wk : Wv;
        const float* bsrc = (w < 4) ? bk : bv;
        float* dst = (w < 4) ? kh : vh;
        const int j0 = (w & 3) * 16;
        float4 pv = *reinterpret_cast<const float4*>(prS + l * 4);
#pragma unroll
        for (int jj = 0; jj < 16; jj++) {
            int j = j0 + jj;
            float4 w4 = *reinterpret_cast<const float4*>(Wsrc + (h * 64 + j) * Dn + l * 4);
            float s = w4.x * pv.x + w4.y * pv.y + w4.z * pv.z + w4.w * pv.w;
#pragma unroll
            for (int o = 16; o; o >>= 1) s += __shfl_xor_sync(0xffffffffu, s, o);
            if (l == 0) dst[j] = s + bsrc[h * 64 + j];
        }
    }
    __syncthreads();

    if (w == 0) {   // gc[col]
        float s = bq[h * 64 + l] * kh[l] + bq[h * 64 + 32 + l] * kh[32 + l];
#pragma unroll
        for (int o = 16; o; o >>= 1) s += __shfl_xor_sync(0xffffffffu, s, o);
        if (l == 0) gc[col] = s * 0.125f;
    }

    if (t < Dn) {
        // imgA column (k = t)
        float a = 0.f;
#pragma unroll 16
        for (int j = 0; j < 64; j++) a += Wq[(h * 64 + j) * Dn + t] * kh[j];  // coalesced over t
        a *= 0.125f;
        uint32_t hi2, lo2;
        {   // scalar split
            __nv_bfloat16 hb = __float2bfloat16(a);
            float fh = __bfloat162float(hb);
            __nv_bfloat16 lb = __float2bfloat16(a - fh);
            imgA_hi[col * XSTR + t] = __bfloat16_as_ushort(hb);
            imgA_lo[col * XSTR + t] = __bfloat16_as_ushort(lb);
        }
        // imgW column (straight copy of Wfc row)
        float wv = Wfc[col * Dn + t];
        {
            __nv_bfloat16 hb = __float2bfloat16(wv);
            float fh = __bfloat162float(hb);
            __nv_bfloat16 lb = __float2bfloat16(wv - fh);
            imgW_hi[col * XSTR + t] = __bfloat16_as_ushort(hb);
            imgW_lo[col * XSTR + t] = __bfloat16_as_ushort(lb);
        }
        (void)hi2; (void)lo2;
        if (t < 8) {   // zero the k-pad of row `col` in all images (determinism)
            imgA_hi[col * XSTR + Dn + t] = 0; imgA_lo[col * XSTR + Dn + t] = 0;
            imgB_hi[col * XSTR + Dn + t] = 0; imgB_lo[col * XSTR + Dn + t] = 0;
            imgW_hi[col * XSTR + Dn + t] = 0; imgW_lo[col * XSTR + Dn + t] = 0;
        }
    } else {
        const int j2 = t - Dn;
        const float4* wo = reinterpret_cast<const float4*>(Wo + j2 * Dn + h * 64);
        float s = 0.f;
#pragma unroll
        for (int q = 0; q < 16; q++) {
            float4 w4 = wo[q];
            float4 v4 = *reinterpret_cast<const float4*>(vh + q * 4);
            s += w4.x * v4.x + w4.y * v4.y + w4.z * v4.z + w4.w * v4.w;
        }
        __nv_bfloat16 hb = __float2bfloat16(s);
        float fh = __bfloat162float(hb);
        __nv_bfloat16 lb = __float2bfloat16(s - fh);
        imgB_hi[j2 * XSTR + col] = __bfloat16_as_ushort(hb);   // [n=j][k=col]
        imgB_lo[j2 * XSTR + col] = __bfloat16_as_ushort(lb);
    }
}

// ============================================================
// Main kernel smem layout (bytes)
// ============================================================
#define SM_GC   0
#define SM_BO   512
#define SM_BFC  1024
#define SM_AHI  1536                         // 32*136*2 = 8704
#define SM_ALO  (SM_AHI + TM * XSTR * 2)     // 10240
#define SM_SC   (SM_ALO + TM * XSTR * 2)     // 18944 ; 32*132*4 = 16896
#define SM_B0H  (SM_SC + TM * SSTR * 4)      // 35840 ; 128*136*2 = 34816
#define SM_B0L  (SM_B0H + Dn * XSTR * 2)
#define SM_B1H  (SM_B0L + Dn * XSTR * 2)
#define SM_B1L  (SM_B1H + Dn * XSTR * 2)
#define SM_TOT  (SM_B1L + Dn * XSTR * 2)     // 175104 B

__device__ __forceinline__ void cpa_tile(uint32_t sdst, const uint16_t* src, int tid) {
    // copy 128*XSTR bf16 = 34816 B = 2176 x 16B chunks
#pragma unroll
    for (int i = 0; i < 9; i++) {
        int idx = tid + i * NTHR;
        if (idx < (Dn * XSTR * 2) / 16)
            asm volatile("cp.async.cg.shared.global [%0], [%1], 16;"
                         :: "r"(sdst + idx * 16), "l"((const char*)src + idx * 16));
    }
}
__device__ __forceinline__ void cp16(uint32_t d, const void* s) {
    asm volatile("cp.async.ca.shared.global [%0], [%1], 16;" :: "r"(d), "l"(s));
}
__device__ __forceinline__ uint32_t smem_to_u32(const void* p) {
    uint32_t a;
    asm("{ .reg .u64 t; cvta.to.shared.u64 t, %1; cvt.u32.u64 %0, t; }" : "=r"(a) : "l"(p));
    return a;
}

// 3-pass split MMA: d += Ahi*Bhi + Ahi*Blo + Alo*Bhi  (each 16x32x128, per warp)
__device__ __forceinline__ void mma_stage(
    const uint16_t* __restrict__ Ah, const uint16_t* __restrict__ Al,
    const uint16_t* __restrict__ Bh, const uint16_t* __restrict__ Bl,
    int m0, int n0, int g, int tg, float d[4][4])
{
#pragma unroll
    for (int nt = 0; nt < 4; nt++)
#pragma unroll
        for (int i = 0; i < 4; i++) d[nt][i] = 0.f;

#pragma unroll
    for (int p = 0; p < 3; p++) {
        const uint16_t* A = (p == 2) ? Al : Ah;
        const uint16_t* B = (p == 1) ? Bl : Bh;
#pragma unroll
        for (int kk = 0; kk < 8; kk++) {
            const uint16_t* ap = A + (m0 + g) * XSTR + kk * 16 + tg * 2;
            uint32_t a0 = *reinterpret_cast<const uint32_t*>(ap);
            uint32_t a1 = *reinterpret_cast<const uint32_t*>(ap + 8 * XSTR);
            uint32_t a2 = *reinterpret_cast<const uint32_t*>(ap + 8);
            uint32_t a3 = *reinterpret_cast<const uint32_t*>(ap + 8 * XSTR + 8);
#pragma unroll
            for (int nt = 0; nt < 4; nt++) {
                const uint16_t* bp = B + (n0 + nt * 8 + g) * XSTR + kk * 16 + tg * 2;
                uint32_t b0 = *reinterpret_cast<const uint32_t*>(bp);
                uint32_t b1 = *reinterpret_cast<const uint32_t*>(bp + 8);
                asm volatile(
                    "mma.sync.aligned.m16n8k16.row.col.f32.bf16.bf16.f32 "
                    "{%0,%1,%2,%3}, {%4,%5,%6,%7}, {%8,%9}, {%0,%1,%2,%3};"
                    : "+f"(d[nt][0]), "+f"(d[nt][1]), "+f"(d[nt][2]), "+f"(d[nt][3])
                    : "r"(a0), "r"(a1), "r"(a2), "r"(a3), "r"(b0), "r"(b1));
            }
        }
    }
}

// ============================================================
// Main fused kernel: grid 128 (TM=32 rows), 256 threads.
// Warp w: m0 = (w>>2)*16 rows, n0 = (w&3)*32 cols.
// ============================================================
__global__ __launch_bounds__(NTHR) void gnn_mma_kernel(
    const float* __restrict__ x,
    const float* __restrict__ bo, const float* __restrict__ bfc,
    float* __restrict__ outP, float* __restrict__ outH)
{
    extern __shared__ char smem[];
    const uint32_t su = smem_to_u32(smem);
    uint16_t* Ah = reinterpret_cast<uint16_t*>(smem + SM_AHI);
    uint16_t* Al = reinterpret_cast<uint16_t*>(smem + SM_ALO);
    float*    sc = reinterpret_cast<float*>(smem + SM_SC);
    const uint16_t* B0h = reinterpret_cast<const uint16_t*>(smem + SM_B0H);
    const uint16_t* B0l = reinterpret_cast<const uint16_t*>(smem + SM_B0L);
    const uint16_t* B1h = reinterpret_cast<const uint16_t*>(smem + SM_B1H);
    const uint16_t* B1l = reinterpret_cast<const uint16_t*>(smem + SM_B1L);

    const int tid = threadIdx.x;
    const int w = tid >> 5, lane = tid & 31;
    const int g = lane >> 2, tg = lane & 3;
    const int m0 = (w >> 2) * 16, n0 = (w & 3) * 32;
    const int row0 = blockIdx.x * TM;

    // -------- group 1: biases + stage-1 B operand (imgA) --------
    cpa_tile(su + SM_B0H, imgA_hi, tid);
    cpa_tile(su + SM_B0L, imgA_lo, tid);
    if (tid < 32)      cp16(su + SM_GC  + tid * 16,        (const char*)gc  + tid * 16);
    else if (tid < 64) cp16(su + SM_BO  + (tid - 32) * 16, (const char*)bo  + (tid - 32) * 16);
    else if (tid < 96) cp16(su + SM_BFC + (tid - 64) * 16, (const char*)bfc + (tid - 64) * 16);
    CP_COMMIT();
    // -------- group 2: stage-2 B operand (imgB) --------
    cpa_tile(su + SM_B1H, imgB_hi, tid);
    cpa_tile(su + SM_B1L, imgB_lo, tid);
    CP_COMMIT();

    // -------- stage x -> A tiles (split bf16, padded k-major) --------
    {
        const float4* xg = reinterpret_cast<const float4*>(x + (size_t)row0 * Dn);
#pragma unroll
        for (int i = 0; i < 4; i++) {
            int idx = tid + i * NTHR;          // 0..1023 quad of 32x128 tile
            int r = idx >> 5, k0 = (idx & 31) * 4;
            float4 v = xg[idx];
            unsigned long long hi, lo;
            cvt_split4(v.x, v.y, v.z, v.w, hi, lo);
            *reinterpret_cast<unsigned long long*>(Ah + r * XSTR + k0) = hi;
            *reinterpret_cast<unsigned long long*>(Al + r * XSTR + k0) = lo;
        }
    }
    CP_WAIT(1);               // group 1 done (biases + B0); group 2 may be in flight
    __syncthreads();

    float d[4][4];

    // ==================== stage 1: scores = x @ A + gc ====================
    mma_stage(Ah, Al, B0h, B0l, m0, n0, g, tg, d);
    {
        const float* gcS = reinterpret_cast<const float*>(smem + SM_GC);
#pragma unroll
        for (int nt = 0; nt < 4; nt++) {
            int c = n0 + nt * 8 + tg * 2;
            float2 bv = *reinterpret_cast<const float2*>(gcS + c);
            *reinterpret_cast<float2*>(sc + (m0 + g) * SSTR + c)
                = make_float2(d[nt][0] + bv.x, d[nt][1] + bv.y);
            *reinterpret_cast<float2*>(sc + (m0 + g + 8) * SSTR + c)
                = make_float2(d[nt][2] + bv.x, d[nt][3] + bv.y);
        }
    }
    __syncthreads();          // all stage-1 work done: B0 & A free for rewrite

    // -------- group 3: stage-3 B operand (imgW) -> B0 ; softmax -> alpha in A ----
    cpa_tile(su + SM_B0H, imgW_hi, tid);
    cpa_tile(su + SM_B0L, imgW_lo, tid);
    CP_COMMIT();
    if (tid < 64) {           // one (row, head) per thread: softmax over 64 proxies
        const int r = tid >> 1, hh = tid & 1;
        const float* sp = sc + r * SSTR + hh * 64;
        float v[64];
        float mx = -1e30f;
#pragma unroll
        for (int j = 0; j < 64; j++) { v[j] = sp[j]; mx = fmaxf(mx, v[j]); }
        float sum = 0.f;
#pragma unroll
        for (int j = 0; j < 64; j++) { v[j] = __expf(v[j] - mx); sum += v[j]; }
        float inv = __fdividef(1.f, sum);
#pragma unroll
        for (int q = 0; q < 16; q++) {
            unsigned long long hi, lo;
            cvt_split4(v[4*q] * inv, v[4*q+1] * inv, v[4*q+2] * inv, v[4*q+3] * inv, hi, lo);
            int k0 = hh * 64 + 4 * q;
            *reinterpret_cast<unsigned long long*>(Ah + r * XSTR + k0) = hi;
            *reinterpret_cast<unsigned long long*>(Al + r * XSTR + k0) = lo;
        }
    }
    CP_WAIT(1);               // group 2 (B1 = imgB) done; group 3 may be in flight
    __syncthreads();

    // ==================== stage 2: h = relu(alpha @ B + bo) ====================
    mma_stage(Ah, Al, B1h, B1l, m0, n0, g, tg, d);
    __syncthreads();          // all stage-2 A reads done before overwrite
    {
        const float* boS = reinterpret_cast<const float*>(smem + SM_BO);
#pragma unroll
        for (int nt = 0; nt < 4; nt++) {
            int c = n0 + nt * 8 + tg * 2;
            float2 bv = *reinterpret_cast<const float2*>(boS + c);
            float h00 = fmaxf(d[nt][0] + bv.x, 0.f), h01 = fmaxf(d[nt][1] + bv.y, 0.f);
            float h10 = fmaxf(d[nt][2] + bv.x, 0.f), h11 = fmaxf(d[nt][3] + bv.y, 0.f);
            *reinterpret_cast<float2*>(outH + (size_t)(row0 + m0 + g) * Dn + c)
                = make_float2(h00, h01);
            *reinterpret_cast<float2*>(outH + (size_t)(row0 + m0 + g + 8) * Dn + c)
                = make_float2(h10, h11);
            uint32_t hi, lo;
            cvt_split2(h00, h01, hi, lo);
            *reinterpret_cast<uint32_t*>(Ah + (m0 + g) * XSTR + c) = hi;
            *reinterpret_cast<uint32_t*>(Al + (m0 + g) * XSTR + c) = lo;
            cvt_split2(h10, h11, hi, lo);
            *reinterpret_cast<uint32_t*>(Ah + (m0 + g + 8) * XSTR + c) = hi;
            *reinterpret_cast<uint32_t*>(Al + (m0 + g + 8) * XSTR + c) = lo;
        }
    }
    CP_WAIT(0);               // group 3 (B0 = imgW) done
    __syncthreads();

    // ==================== stage 3: preds = h @ Wfc^T + bfc ====================
    mma_stage(Ah, Al, B0h, B0l, m0, n0, g, tg, d);
    {
        const float* bfcS = reinterpret_cast<const float*>(smem + SM_BFC);
#pragma unroll
        for (int nt = 0; nt < 4; nt++) {
            int c = n0 + nt * 8 + tg * 2;
            float2 bv = *reinterpret_cast<const float2*>(bfcS + c);
            *reinterpret_cast<float2*>(outP + (size_t)(row0 + m0 + g) * Dn + c)
                = make_float2(d[nt][0] + bv.x, d[nt][1] + bv.y);
            *reinterpret_cast<float2*>(outP + (size_t)(row0 + m0 + g + 8) * Dn + c)
                = make_float2(d[nt][2] + bv.x, d[nt][3] + bv.y);
        }
    }
}

// ============================================================
// launcher (graph-capturable: kernel launches only)
// ============================================================
extern "C" void kernel_launch(void* const* d_in, const int* in_sizes, int n_in,
                              void* d_out, int out_size) {
    const float* x       = (const float*)d_in[0];
    const float* proxies = (const float*)d_in[1];
    const float* Wq  = (const float*)d_in[2];
    const float* bq  = (const float*)d_in[3];
    const float* Wk  = (const float*)d_in[4];
    const float* bk  = (const float*)d_in[5];
    const float* Wv  = (const float*)d_in[6];
    const float* bv  = (const float*)d_in[7];
    const float* Wo  = (const float*)d_in[8];
    const float* bo  = (const float*)d_in[9];
    const float* Wfc = (const float*)d_in[10];
    const float* bfc = (const float*)d_in[11];
    // d_in[12] = edge_index : dense bipartite structure known -> unused

    float* outP = (float*)d_out;                 // preds[P:]  (S x D)
    float* outH = outP + (size_t)out_size / 2;   // h[P:]      (S x D)

    pre_all_kernel<<<Dn, NTHR>>>(proxies, Wq, bq, Wk, bk, Wv, bv, Wo, Wfc);

    cudaFuncSetAttribute(gnn_mma_kernel,
                         cudaFuncAttributeMaxDynamicSharedMemorySize, SM_TOT);
    gnn_mma_kernel<<<Sn / TM, NTHR, SM_TOT>>>(x, bo, bfc, outP, outH);
}